// round 3
// baseline (speedup 1.0000x reference)
#include <cuda_runtime.h>

// Problem constants (fixed by setup_inputs)
#define BSZ 32
#define CIc 32
#define COc 32
#define NIc 8
#define NOc 8
#define PP  256   // 16x16 spatial
#define KKc 72    // NI*3*3

// Scratch (device globals: allocation-free per harness rules)
__device__ short g_votes[BSZ*COc*CIc*NOc*PP];   // [b][co][ci][no][p], value*256 (exact)
__device__ float g_logits[BSZ*CIc*COc*PP];      // [b][ci][co][p]
__device__ float g_smax[BSZ*CIc];
__device__ float g_ssum[BSZ*CIc];

__device__ __forceinline__ void ffma2(unsigned long long &acc, unsigned long long a, unsigned long long b) {
    asm("fma.rn.f32x2 %0, %1, %2, %0;" : "+l"(acc) : "l"(a), "l"(b));
}
__device__ __forceinline__ float lo32(unsigned long long v){ return __uint_as_float((unsigned)(v & 0xffffffffu)); }
__device__ __forceinline__ float hi32(unsigned long long v){ return __uint_as_float((unsigned)(v >> 32)); }

// ---------------------------------------------------------------------------
// Kernel 1: conv -> quantized votes (int16) + iteration-1 logits (exact ints)
// block = (b, ci). Register-tiled GEMM: D[p=256, o=256] = X[p,72] * W[72,o].
// Thread tile 4p x 8o, FFMA2 pairs along k. smem: W^T [k2][o], im2col X [k2][p].
// ---------------------------------------------------------------------------
__global__ void __launch_bounds__(256) conv_votes_kernel(
    const float* __restrict__ x, const float* __restrict__ w,
    const float* __restrict__ cb, const float* __restrict__ bias)
{
    extern __shared__ char sh[];
    float2* w2  = (float2*)sh;                   // [36][256] float2 = 73728 B
    float2* xim = (float2*)(sh + 73728);         // [36][256] float2 = 73728 B
    float*  xp  = (float*)(sh + 147456);         // padded tile 8*18*18 = 10368 B
    float*  cbs = (float*)(sh + 157824);         // 256 floats
    int*    a1s = (int*)(sh + 158848);           // 256 ints

    const int t  = threadIdx.x;
    const int b  = blockIdx.x >> 5, ci = blockIdx.x & 31;

    // --- weight transpose: w2[k2][o] = (w[o][2k2], w[o][2k2+1]) ---
    {
        const float2* wg = (const float2*)(w + t*KKc);   // this thread's o = t
        #pragma unroll
        for (int i = 0; i < 36; i++) w2[i*256 + t] = wg[i];   // conflict-free STS
    }
    cbs[t] = cb[t];
    for (int i = t; i < 8*18*18; i += 256) xp[i] = 0.f;
    __syncthreads();
    {
        const float* xb = x + (b*CIc + ci)*NIc*PP;
        #pragma unroll
        for (int i = 0; i < 8; i++) {
            int idx = t + i*256;
            int ni = idx >> 8, rem = idx & 255;
            xp[ni*324 + ((rem>>4)+1)*18 + (rem&15) + 1] = xb[idx];
        }
    }
    __syncthreads();

    // --- im2col into xim[k2][p] (p = t) ---
    {
        const int y = t >> 4, xc = t & 15;
        #pragma unroll
        for (int k2 = 0; k2 < 36; k2++) {
            const int k0 = 2*k2, k1 = k0 + 1;
            const int ni0 = k0/9, r0 = k0%9, ky0 = r0/3, kx0 = r0%3;
            const int ni1 = k1/9, r1 = k1%9, ky1 = r1/3, kx1 = r1%3;
            float a  = xp[ni0*324 + (y+ky0)*18 + xc + kx0];
            float bb = xp[ni1*324 + (y+ky1)*18 + xc + kx1];
            xim[k2*256 + t] = make_float2(a, bb);
        }
    }

    // iteration-1 activation: route==0 -> preact = bias -> quant -> squash -> quant
    if (t < 32) {
        float pv[8]; float ss = 0.f;
        #pragma unroll
        for (int no = 0; no < 8; no++) {
            float q = rintf(__fmul_rn(bias[t*8+no], 256.f)) * 0.00390625f;
            pv[no] = q;
            ss = __fadd_rn(ss, __fmul_rn(q, q));
        }
        float n   = sqrtf(ss);
        float den = __fadd_rn(1.f, __fmul_rn(n, n));
        #pragma unroll
        for (int no = 0; no < 8; no++) {
            float a = __fdiv_rn(__fmul_rn(pv[no], n), den);
            a1s[t*8+no] = __float2int_rn(__fmul_rn(a, 256.f));
        }
    }
    __syncthreads();

    const int lane = t & 31;
    const int warp = t >> 5;
    short* vbase = g_votes + ((b*32)*32 + ci)*2048;   // + co*65536 + no*256 + p
    float* lbase = g_logits + ((b*32 + ci)*32)*256;   // + co*256 + p

    #pragma unroll 1
    for (int ppass = 0; ppass < 2; ppass++) {
        const int pbase = ppass*128 + lane;
        #pragma unroll 1
        for (int opass = 0; opass < 4; opass++) {
            const int obase = warp*32 + opass*8;
            unsigned long long acc[4][8] = {};
            #pragma unroll 12
            for (int k2 = 0; k2 < 36; k2++) {
                const float2* xrow = xim + k2*256;
                unsigned long long xv[4];
                #pragma unroll
                for (int i = 0; i < 4; i++)
                    xv[i] = *(const unsigned long long*)&xrow[pbase + 32*i];
                const ulonglong2* wrow = (const ulonglong2*)(w2 + k2*256 + obase);
                #pragma unroll
                for (int j = 0; j < 4; j++) {
                    ulonglong2 wv = wrow[j];   // broadcast LDS.128: 2 outputs' k-pairs
                    #pragma unroll
                    for (int i = 0; i < 4; i++) {
                        ffma2(acc[i][2*j],   xv[i], wv.x);
                        ffma2(acc[i][2*j+1], xv[i], wv.y);
                    }
                }
            }
            const int co = obase >> 3;    // obase is a multiple of 8
            #pragma unroll
            for (int i = 0; i < 4; i++) {
                const int p = pbase + 32*i;
                int dsum = 0;
                #pragma unroll
                for (int no = 0; no < 8; no++) {
                    const int o = obase + no;
                    float v = __fadd_rn(__fadd_rn(lo32(acc[i][no]), hi32(acc[i][no])), cbs[o]);
                    int vi = __float2int_rn(v * 256.f);   // quant(votes), half-even
                    vbase[co*65536 + no*256 + p] = (short)vi;
                    dsum += a1s[o] * vi;                  // iter-1 distances (exact int)
                }
                // logits1 = rint(dsum/256)/256, exact in fp32 (|dsum| << 2^24)
                lbase[co*256 + p] = rintf((float)dsum * 0.00390625f) * 0.00390625f;
            }
        }
    }
}

// ---------------------------------------------------------------------------
// Kernel 2: softmax stats per (b, ci) over 8192 logits
// ---------------------------------------------------------------------------
__global__ void __launch_bounds__(256) softmax_kernel()
{
    const int row = blockIdx.x;            // b*32 + ci
    const float* lp = g_logits + row*8192;
    const int t = threadIdx.x;
    float fl[32];
    #pragma unroll
    for (int i = 0; i < 32; i++) fl[i] = lp[i*256 + t];
    float m = fl[0];
    #pragma unroll
    for (int i = 1; i < 32; i++) m = fmaxf(m, fl[i]);
    __shared__ float red[8];
    #pragma unroll
    for (int off = 16; off; off >>= 1) m = fmaxf(m, __shfl_xor_sync(0xffffffffu, m, off));
    if ((t & 31) == 0) red[t >> 5] = m;
    __syncthreads();
    float M = red[0];
    #pragma unroll
    for (int i = 1; i < 8; i++) M = fmaxf(M, red[i]);
    __syncthreads();
    float s = 0.f;
    #pragma unroll
    for (int i = 0; i < 32; i++) s += expf(fl[i] - M);
    #pragma unroll
    for (int off = 16; off; off >>= 1) s += __shfl_xor_sync(0xffffffffu, s, off);
    if ((t & 31) == 0) red[t >> 5] = s;
    __syncthreads();
    if (t == 0) {
        float S = red[0];
        for (int i = 1; i < 8; i++) S += red[i];
        g_smax[row] = M;
        g_ssum[row] = S;
    }
}

// ---------------------------------------------------------------------------
// Kernel 3: fused routing iteration. block = (b, co, p-half); 128 threads.
// 64KB vote tile staged in SMEM -> 3 blocks/SM (overlap staging with compute).
//   pass1: route (softmax+quant) -> preactivate (exact int) -> squash -> activation
//   pass2: agreement distances -> logits update (skipped on last iteration)
// ---------------------------------------------------------------------------
__global__ void __launch_bounds__(128) route_kernel(
    const float* __restrict__ bias, float* __restrict__ out, int last)
{
    extern __shared__ char shb[];
    short* sv    = (short*)shb;                 // [32ci][8no][128p] = 65536 B
    float* smaxs = (float*)(shb + 65536);       // 32
    float* ssums = (float*)(shb + 65664);       // 32
    float* sb    = (float*)(shb + 65792);       // 8

    const int t   = threadIdx.x;                // p index within half
    const int blk = blockIdx.x;                 // (b*32+co)*2 + ph
    const int bco = blk >> 1, ph = blk & 1;
    const int b   = bco >> 5, co = bco & 31;

    {
        const short* src0 = g_votes + bco*65536 + ph*128;
        uint4* dst = (uint4*)sv;
        #pragma unroll
        for (int r = 0; r < 32; r++) {
            int idx = r*128 + t;           // 0..4095 uint4
            int cino = idx >> 4, ch = idx & 15;
            dst[idx] = *(const uint4*)(src0 + cino*256 + ch*8);
        }
    }
    if (t < 32) { smaxs[t] = g_smax[b*32 + t]; ssums[t] = g_ssum[b*32 + t]; }
    if (t < 8)  sb[t] = bias[co*8 + t];
    __syncthreads();

    float l[32];
    int S[8] = {0,0,0,0,0,0,0,0};
    const float* lgp = g_logits + (b*32)*8192 + co*256 + ph*128 + t;
    #pragma unroll
    for (int c = 0; c < 32; c++) {
        float lv = lgp[c*8192];
        l[c] = lv;
        float e = expf(lv - smaxs[c]);
        int r = __float2int_rn(__fmul_rn(__fdiv_rn(e, ssums[c]), 256.f)); // quant(route)*256
        if (r) {
            #pragma unroll
            for (int no = 0; no < 8; no++)
                S[no] += r * (int)sv[(c*8 + no)*128 + t];
        }
    }
    float pq[8]; float ss = 0.f;
    #pragma unroll
    for (int no = 0; no < 8; no++) {
        // preactivate = S/65536 + bias (S/65536 exact), then quant
        float pre = __fadd_rn(__fmul_rn((float)S[no], 1.52587890625e-05f), sb[no]);
        float q = rintf(__fmul_rn(pre, 256.f)) * 0.00390625f;
        pq[no] = q;
        ss = __fadd_rn(ss, __fmul_rn(q, q));
    }
    float n   = sqrtf(ss);
    float den = __fadd_rn(1.f, __fmul_rn(n, n));
    int ai[8];
    #pragma unroll
    for (int no = 0; no < 8; no++) {
        float a = __fdiv_rn(__fmul_rn(pq[no], n), den);   // squash
        int q = __float2int_rn(__fmul_rn(a, 256.f));      // quant(activation)*256
        ai[no] = q;
        out[(bco*8 + no)*256 + ph*128 + t] = (float)q * 0.00390625f;
    }
    if (!last) {
        float* lw = g_logits + (b*32)*8192 + co*256 + ph*128 + t;
        #pragma unroll
        for (int c = 0; c < 32; c++) {
            int m = 0;
            #pragma unroll
            for (int no = 0; no < 8; no++)
                m += ai[no] * (int)sv[(c*8 + no)*128 + t];   // distances (exact int)
            float lg = __fadd_rn(l[c], __fmul_rn((float)m, 1.52587890625e-05f)); // exact
            lw[c*8192] = rintf(__fmul_rn(lg, 256.f)) * 0.00390625f;
        }
    }
}

// ---------------------------------------------------------------------------
extern "C" void kernel_launch(void* const* d_in, const int* in_sizes, int n_in,
                              void* d_out, int out_size)
{
    const float* x    = (const float*)d_in[0];
    const float* w    = (const float*)d_in[1];
    const float* cb   = (const float*)d_in[2];
    const float* bias = (const float*)d_in[3];
    float* out = (float*)d_out;
    (void)in_sizes; (void)n_in; (void)out_size;

    const int CONV_SMEM  = 159872;
    const int ROUTE_SMEM = 65824;
    cudaFuncSetAttribute(conv_votes_kernel, cudaFuncAttributeMaxDynamicSharedMemorySize, CONV_SMEM);
    cudaFuncSetAttribute(route_kernel,      cudaFuncAttributeMaxDynamicSharedMemorySize, ROUTE_SMEM);

    conv_votes_kernel<<<1024, 256, CONV_SMEM>>>(x, w, cb, bias);  // + iteration 1 (folded)
    softmax_kernel<<<1024, 256>>>();                              // iteration 2
    route_kernel<<<2048, 128, ROUTE_SMEM>>>(bias, out, 0);
    softmax_kernel<<<1024, 256>>>();                              // iteration 3
    route_kernel<<<2048, 128, ROUTE_SMEM>>>(bias, out, 1);
}

// round 5
// speedup vs baseline: 1.2558x; 1.2558x over previous
#include <cuda_runtime.h>
#include <cuda_fp16.h>
#include <cstdint>

#define BSZ 32
#define CIc 32
#define PP  256

__device__ short g_votes[BSZ*32*CIc*8*PP];   // [b][co][ci][no][p], value*256 (exact)
__device__ float g_logits[BSZ*CIc*32*PP];    // [b][ci][co][p]
__device__ float g_smax[BSZ*CIc];
__device__ float g_ssum[BSZ*CIc];

// ---------------- helpers ----------------
static __device__ __forceinline__ uint32_t smem_u32(const void* p) {
    uint32_t a;
    asm("{ .reg .u64 t; cvta.to.shared.u64 t, %1; cvt.u32.u64 %0, t; }" : "=r"(a) : "l"(p));
    return a;
}

#define MMA16816(d, a, b) \
    asm volatile("mma.sync.aligned.m16n8k16.row.col.f32.f16.f16.f32 " \
        "{%0,%1,%2,%3}, {%4,%5,%6,%7}, {%8,%9}, {%0,%1,%2,%3};" \
        : "+f"((d)[0]), "+f"((d)[1]), "+f"((d)[2]), "+f"((d)[3]) \
        : "r"((a)[0]), "r"((a)[1]), "r"((a)[2]), "r"((a)[3]), "r"((b)[0]), "r"((b)[1]))

#define LDMX4(r0, r1, r2, r3, addr) \
    asm volatile("ldmatrix.sync.aligned.m8n8.x4.shared.b16 {%0,%1,%2,%3}, [%4];" \
        : "=r"(r0), "=r"(r1), "=r"(r2), "=r"(r3) : "r"(addr))

static __device__ __forceinline__ uint32_t packh(__half a, __half b) {
    return (uint32_t)__half_as_ushort(a) | ((uint32_t)__half_as_ushort(b) << 16);
}
// rn fp16 2-term split of a float pair; returns hi pair, writes lo pair.
static __device__ __forceinline__ uint32_t packsplit(float f0, float f1, uint32_t &lo) {
    __half h0 = __float2half_rn(f0), h1 = __float2half_rn(f1);
    __half l0 = __float2half_rn(__fsub_rn(f0, __half2float(h0)));
    __half l1 = __float2half_rn(__fsub_rn(f1, __half2float(h1)));
    lo = packh(l0, l1);
    return packh(h0, h1);
}

// smem layout (bytes)
#define BHI_OFF    0u         // [256 o][176B rows] fp16 hi
#define BLO_OFF    45056u
#define XS_OFF     90112u     // padded x tile [8ni][18][18] floats
#define STAGE_OFF  100480u    // 8 warps * 32p*72o shorts
#define CBS_OFF    137344u
#define A1S_OFF    138368u
#define KLUT_OFF   139392u
#define CONV_SMEM  139680

// ---------------------------------------------------------------------------
// Kernel 1: fp16-split mma.sync conv -> int16 votes + iteration-1 logits.
// block = (b, ci): D[256p, 256o] = X[256,72] * W^T, K padded to 80.
// Warp tile: 32p x 64o per pass, 4 passes. 3 products: hh, hl, lh.
// ---------------------------------------------------------------------------
__global__ void __launch_bounds__(256, 1) conv_votes_kernel(
    const float* __restrict__ x, const float* __restrict__ w,
    const float* __restrict__ cb, const float* __restrict__ bias)
{
    extern __shared__ char sh[];
    float* xs  = (float*)(sh + XS_OFF);
    float* cbs = (float*)(sh + CBS_OFF);
    int*   a1s = (int*)(sh + A1S_OFF);
    int*   klut= (int*)(sh + KLUT_OFF);
    const uint32_t smb = smem_u32(sh);

    const int t = threadIdx.x;
    const int wid = t >> 5, lane = t & 31;
    const int b = blockIdx.x >> 5, ci = blockIdx.x & 31;

    // --- fills ---
    for (int i = t; i < 2592; i += 256) xs[i] = 0.f;
    cbs[t] = cb[t];
    if (t < 72) { int ni = t/9, r = t%9; klut[t] = ni*324 + (r/3)*18 + (r%3); }
    if (t < 32) {   // iteration-1 activation from bias (quant(route)==0)
        float pv[8]; float ss = 0.f;
        #pragma unroll
        for (int no = 0; no < 8; no++) {
            float q = rintf(__fmul_rn(bias[t*8+no], 256.f)) * 0.00390625f;
            pv[no] = q; ss = __fadd_rn(ss, __fmul_rn(q, q));
        }
        float n = sqrtf(ss);
        float den = __fadd_rn(1.f, __fmul_rn(n, n));
        #pragma unroll
        for (int no = 0; no < 8; no++) {
            float a = __fdiv_rn(__fmul_rn(pv[no], n), den);
            a1s[t*8+no] = __float2int_rn(__fmul_rn(a, 256.f));
        }
    }
    // B fill: this thread's o = t; W row -> hi/lo fp16, 176B row stride
    {
        const float4* wr = (const float4*)(w + t*72);
        char* bh = sh + BHI_OFF + t*176;
        char* bl = sh + BLO_OFF + t*176;
        #pragma unroll
        for (int q = 0; q < 18; q++) {
            float4 v = wr[q];
            uint32_t l0, l1;
            uint32_t h0 = packsplit(v.x, v.y, l0);
            uint32_t h1 = packsplit(v.z, v.w, l1);
            *(uint2*)(bh + q*8) = make_uint2(h0, h1);
            *(uint2*)(bl + q*8) = make_uint2(l0, l1);
        }
        *(uint4*)(bh + 144) = make_uint4(0,0,0,0);   // k pad 72..79
        *(uint4*)(bl + 144) = make_uint4(0,0,0,0);
    }
    __syncthreads();
    {   // x interior (zeros already placed for halo)
        const float* xb = x + (b*CIc + ci)*8*PP;
        #pragma unroll
        for (int i = 0; i < 8; i++) {
            int idx = t + i*256;
            int ni = idx >> 8, rem = idx & 255;
            xs[ni*324 + ((rem>>4)+1)*18 + (rem&15) + 1] = xb[idx];
        }
    }
    __syncthreads();

    // --- A fragments in registers (hi/lo), all 5 k-chunks x 2 m-tiles ---
    const int wrow = wid*32;
    const int lane2 = (lane & 3)*2;
    uint32_t ah[5][2][4], al[5][2][4];
    #pragma unroll
    for (int kc = 0; kc < 5; kc++) {
        const int kb = kc*16 + lane2;
        #pragma unroll
        for (int mt = 0; mt < 2; mt++) {
            const int r = wrow + (lane >> 2) + mt*16;
            const int xyb0 = (r >> 4)*18 + (r & 15);
            const int r8 = r + 8;
            const int xyb8 = (r8 >> 4)*18 + (r8 & 15);
            float f00 = (kb   < 72) ? xs[klut[kb]   + xyb0] : 0.f;
            float f01 = (kb+1 < 72) ? xs[klut[kb+1] + xyb0] : 0.f;
            float f10 = (kb   < 72) ? xs[klut[kb]   + xyb8] : 0.f;
            float f11 = (kb+1 < 72) ? xs[klut[kb+1] + xyb8] : 0.f;
            float f20 = (kb+8 < 72) ? xs[klut[kb+8] + xyb0] : 0.f;
            float f21 = (kb+9 < 72) ? xs[klut[kb+9] + xyb0] : 0.f;
            float f30 = (kb+8 < 72) ? xs[klut[kb+8] + xyb8] : 0.f;
            float f31 = (kb+9 < 72) ? xs[klut[kb+9] + xyb8] : 0.f;
            ah[kc][mt][0] = packsplit(f00, f01, al[kc][mt][0]);
            ah[kc][mt][1] = packsplit(f10, f11, al[kc][mt][1]);
            ah[kc][mt][2] = packsplit(f20, f21, al[kc][mt][2]);
            ah[kc][mt][3] = packsplit(f30, f31, al[kc][mt][3]);
        }
    }

    short* stg = (short*)(sh + STAGE_OFF) + wid*2304;   // [32p][72o-pad]

    #pragma unroll 1
    for (int pass = 0; pass < 4; pass++) {
        float acc[2][8][4];
        #pragma unroll
        for (int mt = 0; mt < 2; mt++)
            #pragma unroll
            for (int nt = 0; nt < 8; nt++)
                #pragma unroll
                for (int j = 0; j < 4; j++) acc[mt][nt][j] = 0.f;

        #pragma unroll
        for (int kc = 0; kc < 5; kc++) {
            uint32_t bh[8][2], bl[8][2];
            #pragma unroll
            for (int g = 0; g < 4; g++) {
                const int row = pass*64 + g*16 + (lane & 7) + ((lane >> 4) << 3);
                const uint32_t koff = kc*32 + ((lane >> 3) & 1)*16;
                LDMX4(bh[2*g][0], bh[2*g][1], bh[2*g+1][0], bh[2*g+1][1],
                      smb + BHI_OFF + row*176 + koff);
                LDMX4(bl[2*g][0], bl[2*g][1], bl[2*g+1][0], bl[2*g+1][1],
                      smb + BLO_OFF + row*176 + koff);
            }
            #pragma unroll
            for (int mt = 0; mt < 2; mt++)
                #pragma unroll
                for (int nt = 0; nt < 8; nt++) {
                    MMA16816(acc[mt][nt], ah[kc][mt], bh[nt]);
                    MMA16816(acc[mt][nt], ah[kc][mt], bl[nt]);
                    MMA16816(acc[mt][nt], al[kc][mt], bh[nt]);
                }
        }

        // --- epilogue: quantize to int16 votes, stage [p][o] in smem ---
        #pragma unroll
        for (int mt = 0; mt < 2; mt++)
            #pragma unroll
            for (int nt = 0; nt < 8; nt++) {
                const int c = nt*8 + lane2;
                const int r = (lane >> 2) + mt*16;
                const int o0 = pass*64 + c;
                int v0 = __float2int_rn((acc[mt][nt][0] + cbs[o0])   * 256.f);
                int v1 = __float2int_rn((acc[mt][nt][1] + cbs[o0+1]) * 256.f);
                int v2 = __float2int_rn((acc[mt][nt][2] + cbs[o0])   * 256.f);
                int v3 = __float2int_rn((acc[mt][nt][3] + cbs[o0+1]) * 256.f);
                *(uint32_t*)(stg + r*72 + c)     = (v0 & 0xFFFF) | (v1 << 16);
                *(uint32_t*)(stg + (r+8)*72 + c) = (v2 & 0xFFFF) | (v3 << 16);
            }
        __syncwarp();

        // votes out: vectorized along p (8 shorts = uint4)
        #pragma unroll
        for (int i = 0; i < 8; i++) {
            const int pc = i >> 1;
            const int ol = ((i & 1) << 5) + lane;
            unsigned short vs[8];
            #pragma unroll
            for (int j = 0; j < 8; j++) vs[j] = *(const unsigned short*)(stg + (pc*8 + j)*72 + ol);
            uint4 pk;
            pk.x = vs[0] | ((uint32_t)vs[1] << 16);
            pk.y = vs[2] | ((uint32_t)vs[3] << 16);
            pk.z = vs[4] | ((uint32_t)vs[5] << 16);
            pk.w = vs[6] | ((uint32_t)vs[7] << 16);
            const int o = pass*64 + ol, co = o >> 3, no = o & 7;
            *(uint4*)(g_votes + ((size_t)b << 21) + co*65536 + ci*2048 + no*256 + wrow + pc*8) = pk;
        }
        // iteration-1 logits fold (exact ints)
        #pragma unroll
        for (int i = 0; i < 8; i++) {
            const int task = i*32 + lane;
            const int pl = task >> 3, coi = task & 7;
            uint4 vv = *(const uint4*)(stg + pl*72 + coi*8);
            const int* a1 = a1s + pass*64 + coi*8;
            int dsum = 0;
            dsum += a1[0] * (int)(short)(vv.x & 0xFFFF);
            dsum += a1[1] * ((int)vv.x >> 16);
            dsum += a1[2] * (int)(short)(vv.y & 0xFFFF);
            dsum += a1[3] * ((int)vv.y >> 16);
            dsum += a1[4] * (int)(short)(vv.z & 0xFFFF);
            dsum += a1[5] * ((int)vv.z >> 16);
            dsum += a1[6] * (int)(short)(vv.w & 0xFFFF);
            dsum += a1[7] * ((int)vv.w >> 16);
            g_logits[((b*32 + ci)*32 + pass*8 + coi)*256 + wrow + pl] =
                rintf((float)dsum * 0.00390625f) * 0.00390625f;
        }
        __syncwarp();
    }
}

// ---------------------------------------------------------------------------
// Kernel 2: softmax stats per (b, ci) over 8192 logits
// ---------------------------------------------------------------------------
__global__ void __launch_bounds__(256) softmax_kernel()
{
    const int row = blockIdx.x;
    const float* lp = g_logits + row*8192;
    const int t = threadIdx.x;
    float fl[32];
    #pragma unroll
    for (int i = 0; i < 32; i++) fl[i] = lp[i*256 + t];
    float m = fl[0];
    #pragma unroll
    for (int i = 1; i < 32; i++) m = fmaxf(m, fl[i]);
    __shared__ float red[8];
    #pragma unroll
    for (int off = 16; off; off >>= 1) m = fmaxf(m, __shfl_xor_sync(0xffffffffu, m, off));
    if ((t & 31) == 0) red[t >> 5] = m;
    __syncthreads();
    float M = red[0];
    #pragma unroll
    for (int i = 1; i < 8; i++) M = fmaxf(M, red[i]);
    __syncthreads();
    float s = 0.f;
    #pragma unroll
    for (int i = 0; i < 32; i++) s += expf(fl[i] - M);
    #pragma unroll
    for (int off = 16; off; off >>= 1) s += __shfl_xor_sync(0xffffffffu, s, off);
    if ((t & 31) == 0) red[t >> 5] = s;
    __syncthreads();
    if (t == 0) {
        float S = red[0];
        for (int i = 1; i < 8; i++) S += red[i];
        g_smax[row] = M;
        g_ssum[row] = S;
    }
}

// ---------------------------------------------------------------------------
// Kernel 3: fused routing iteration. block = (b, co, p-half); 128 threads.
// ---------------------------------------------------------------------------
__global__ void __launch_bounds__(128) route_kernel(
    const float* __restrict__ bias, float* __restrict__ out, int last)
{
    extern __shared__ char shb[];
    short* sv    = (short*)shb;                 // [32ci][8no][128p] = 65536 B
    float* smaxs = (float*)(shb + 65536);
    float* ssums = (float*)(shb + 65664);
    float* sb    = (float*)(shb + 65792);

    const int t   = threadIdx.x;
    const int blk = blockIdx.x;
    const int bco = blk >> 1, ph = blk & 1;
    const int b   = bco >> 5, co = bco & 31;

    {
        const short* src0 = g_votes + (size_t)bco*65536 + ph*128;
        uint4* dst = (uint4*)sv;
        #pragma unroll
        for (int r = 0; r < 32; r++) {
            int idx = r*128 + t;
            int cino = idx >> 4, ch = idx & 15;
            dst[idx] = *(const uint4*)(src0 + cino*256 + ch*8);
        }
    }
    if (t < 32) { smaxs[t] = g_smax[b*32 + t]; ssums[t] = g_ssum[b*32 + t]; }
    if (t < 8)  sb[t] = bias[co*8 + t];
    __syncthreads();

    float l[32];
    int S[8] = {0,0,0,0,0,0,0,0};
    const float* lgp = g_logits + (b*32)*8192 + co*256 + ph*128 + t;
    #pragma unroll
    for (int c = 0; c < 32; c++) {
        float lv = lgp[c*8192];
        l[c] = lv;
        float e = expf(lv - smaxs[c]);
        int r = __float2int_rn(__fmul_rn(__fdiv_rn(e, ssums[c]), 256.f));
        if (r) {
            #pragma unroll
            for (int no = 0; no < 8; no++)
                S[no] += r * (int)sv[(c*8 + no)*128 + t];
        }
    }
    float pq[8]; float ss = 0.f;
    #pragma unroll
    for (int no = 0; no < 8; no++) {
        float pre = __fadd_rn(__fmul_rn((float)S[no], 1.52587890625e-05f), sb[no]);
        float q = rintf(__fmul_rn(pre, 256.f)) * 0.00390625f;
        pq[no] = q; ss = __fadd_rn(ss, __fmul_rn(q, q));
    }
    float n   = sqrtf(ss);
    float den = __fadd_rn(1.f, __fmul_rn(n, n));
    int ai[8];
    #pragma unroll
    for (int no = 0; no < 8; no++) {
        float a = __fdiv_rn(__fmul_rn(pq[no], n), den);
        int q = __float2int_rn(__fmul_rn(a, 256.f));
        ai[no] = q;
        out[(bco*8 + no)*256 + ph*128 + t] = (float)q * 0.00390625f;
    }
    if (!last) {
        float* lw = g_logits + (b*32)*8192 + co*256 + ph*128 + t;
        #pragma unroll
        for (int c = 0; c < 32; c++) {
            int m = 0;
            #pragma unroll
            for (int no = 0; no < 8; no++)
                m += ai[no] * (int)sv[(c*8 + no)*128 + t];
            float lg = __fadd_rn(l[c], __fmul_rn((float)m, 1.52587890625e-05f));
            lw[c*8192] = rintf(__fmul_rn(lg, 256.f)) * 0.00390625f;
        }
    }
}

// ---------------------------------------------------------------------------
extern "C" void kernel_launch(void* const* d_in, const int* in_sizes, int n_in,
                              void* d_out, int out_size)
{
    const float* x    = (const float*)d_in[0];
    const float* w    = (const float*)d_in[1];
    const float* cb   = (const float*)d_in[2];
    const float* bias = (const float*)d_in[3];
    float* out = (float*)d_out;
    (void)in_sizes; (void)n_in; (void)out_size;

    const int ROUTE_SMEM = 65824;
    cudaFuncSetAttribute(conv_votes_kernel, cudaFuncAttributeMaxDynamicSharedMemorySize, CONV_SMEM);
    cudaFuncSetAttribute(route_kernel,      cudaFuncAttributeMaxDynamicSharedMemorySize, ROUTE_SMEM);

    conv_votes_kernel<<<1024, 256, CONV_SMEM>>>(x, w, cb, bias);  // + iteration 1 folded
    softmax_kernel<<<1024, 256>>>();                              // iteration 2
    route_kernel<<<2048, 128, ROUTE_SMEM>>>(bias, out, 0);
    softmax_kernel<<<1024, 256>>>();                              // iteration 3
    route_kernel<<<2048, 128, ROUTE_SMEM>>>(bias, out, 1);
}